// round 1
// baseline (speedup 1.0000x reference)
#include <cuda_runtime.h>

#define CN 8192

// Scratch (no cudaMalloc allowed)
__device__ float g_exp[CN];
__device__ float g_contrib[CN];

__global__ void cox_prep_kernel(const float* __restrict__ theta) {
    int j = blockIdx.x * blockDim.x + threadIdx.x;
    if (j < CN) g_exp[j] = expf(theta[j]);
}

// One warp per row i. Streams survtime + exp(theta) as float4 (L1-resident),
// accumulates masked sum, warp-reduces, writes per-i contribution.
__global__ void __launch_bounds__(256) cox_risk_kernel(
    const float* __restrict__ theta,
    const float* __restrict__ sv,
    const float* __restrict__ cen)
{
    int gwarp = (blockIdx.x * blockDim.x + threadIdx.x) >> 5;
    int lane  = threadIdx.x & 31;
    if (gwarp >= CN) return;

    float svi = __ldg(&sv[gwarp]);

    const float4* sv4 = reinterpret_cast<const float4*>(sv);
    const float4* ex4 = reinterpret_cast<const float4*>(g_exp);

    float sum = 0.0f;
    // CN/4 = 2048 float4 elements; 32 lanes -> 64 iterations per lane.
    #pragma unroll 4
    for (int j = lane; j < CN / 4; j += 32) {
        float4 s = __ldg(&sv4[j]);
        float4 e = ex4[j];
        sum += (s.x >= svi) ? e.x : 0.0f;
        sum += (s.y >= svi) ? e.y : 0.0f;
        sum += (s.z >= svi) ? e.z : 0.0f;
        sum += (s.w >= svi) ? e.w : 0.0f;
    }

    // Warp reduction (deterministic order)
    #pragma unroll
    for (int off = 16; off > 0; off >>= 1)
        sum += __shfl_xor_sync(0xffffffffu, sum, off);

    if (lane == 0) {
        float th = __ldg(&theta[gwarp]);
        float c  = __ldg(&cen[gwarp]);
        g_contrib[gwarp] = (th - logf(sum)) * c;
    }
}

// Single-block deterministic tree reduction of the 8192 contributions.
__global__ void __launch_bounds__(1024) cox_reduce_kernel(float* __restrict__ out) {
    __shared__ float sh[1024];
    float s = 0.0f;
    #pragma unroll
    for (int k = threadIdx.x; k < CN; k += 1024) s += g_contrib[k];
    sh[threadIdx.x] = s;
    __syncthreads();
    #pragma unroll
    for (int st = 512; st > 0; st >>= 1) {
        if (threadIdx.x < st) sh[threadIdx.x] += sh[threadIdx.x + st];
        __syncthreads();
    }
    if (threadIdx.x == 0) out[0] = -sh[0] / (float)CN;
}

extern "C" void kernel_launch(void* const* d_in, const int* in_sizes, int n_in,
                              void* d_out, int out_size) {
    const float* hazard_pred = (const float*)d_in[0]; // [N,1] -> N floats
    const float* survtime    = (const float*)d_in[1]; // [N]
    const float* censor      = (const float*)d_in[2]; // [N]
    float* out = (float*)d_out;

    cox_prep_kernel<<<(CN + 255) / 256, 256>>>(hazard_pred);
    cox_risk_kernel<<<CN / 8, 256>>>(hazard_pred, survtime, censor);
    cox_reduce_kernel<<<1, 1024>>>(out);
}

// round 2
// speedup vs baseline: 1.2933x; 1.2933x over previous
#include <cuda_runtime.h>

#define CN   8192
#define NBLK 128
#define NTHR 512            // 16 warps
#define RPW  4              // rows per warp: 128 * 16 * 4 = 8192

__device__ float        g_partial[NBLK];
__device__ unsigned int g_count = 0;

__global__ void __launch_bounds__(NTHR) cox_fused_kernel(
    const float* __restrict__ theta,
    const float* __restrict__ sv,
    const float* __restrict__ cen,
    float* __restrict__ out)
{
    __shared__ float s_ex[CN];                 // 32 KB: exp(theta)
    __shared__ float s_contrib[(NTHR / 32) * RPW];   // 64 row contributions

    const int tid = threadIdx.x;

    // ---- Phase 1: every block computes exp(theta) into its own smem ----
    #pragma unroll
    for (int j = tid; j < CN; j += NTHR)
        s_ex[j] = __expf(theta[j]);
    __syncthreads();

    // ---- Phase 2: scan. Each warp owns RPW=4 rows, lanes partition j ----
    const int warp = tid >> 5;
    const int lane = tid & 31;
    const int row0 = (blockIdx.x * (NTHR / 32) + warp) * RPW;

    const float svi0 = __ldg(&sv[row0 + 0]);
    const float svi1 = __ldg(&sv[row0 + 1]);
    const float svi2 = __ldg(&sv[row0 + 2]);
    const float svi3 = __ldg(&sv[row0 + 3]);

    float a0 = 0.f, a1 = 0.f, a2 = 0.f, a3 = 0.f;

    const float4* sv4 = reinterpret_cast<const float4*>(sv);
    const float4* ex4 = reinterpret_cast<const float4*>(s_ex);

    #pragma unroll 4
    for (int j = lane; j < CN / 4; j += 32) {
        float4 s = __ldg(&sv4[j]);   // global, L1-resident after first pass
        float4 e = ex4[j];           // shared

        if (s.x >= svi0) a0 += e.x;
        if (s.x >= svi1) a1 += e.x;
        if (s.x >= svi2) a2 += e.x;
        if (s.x >= svi3) a3 += e.x;

        if (s.y >= svi0) a0 += e.y;
        if (s.y >= svi1) a1 += e.y;
        if (s.y >= svi2) a2 += e.y;
        if (s.y >= svi3) a3 += e.y;

        if (s.z >= svi0) a0 += e.z;
        if (s.z >= svi1) a1 += e.z;
        if (s.z >= svi2) a2 += e.z;
        if (s.z >= svi3) a3 += e.z;

        if (s.w >= svi0) a0 += e.w;
        if (s.w >= svi1) a1 += e.w;
        if (s.w >= svi2) a2 += e.w;
        if (s.w >= svi3) a3 += e.w;
    }

    // Warp-level reduction over j-partitions (fixed xor-tree order)
    #pragma unroll
    for (int off = 16; off > 0; off >>= 1) {
        a0 += __shfl_xor_sync(0xffffffffu, a0, off);
        a1 += __shfl_xor_sync(0xffffffffu, a1, off);
        a2 += __shfl_xor_sync(0xffffffffu, a2, off);
        a3 += __shfl_xor_sync(0xffffffffu, a3, off);
    }

    if (lane == 0) {
        s_contrib[warp * RPW + 0] = (__ldg(&theta[row0 + 0]) - __logf(a0)) * __ldg(&cen[row0 + 0]);
        s_contrib[warp * RPW + 1] = (__ldg(&theta[row0 + 1]) - __logf(a1)) * __ldg(&cen[row0 + 1]);
        s_contrib[warp * RPW + 2] = (__ldg(&theta[row0 + 2]) - __logf(a2)) * __ldg(&cen[row0 + 2]);
        s_contrib[warp * RPW + 3] = (__ldg(&theta[row0 + 3]) - __logf(a3)) * __ldg(&cen[row0 + 3]);
    }
    __syncthreads();

    // ---- Phase 3: block partial (fixed order), then last-block finalize ----
    if (tid == 0) {
        float bs = 0.f;
        #pragma unroll
        for (int k = 0; k < (NTHR / 32) * RPW; k++) bs += s_contrib[k];
        g_partial[blockIdx.x] = bs;
        __threadfence();

        unsigned int old = atomicAdd(&g_count, 1u);
        if (old == NBLK - 1) {
            // last block: deterministic fixed-order sum of all partials
            float t = 0.f;
            #pragma unroll 8
            for (int b = 0; b < NBLK; b++) t += g_partial[b];
            out[0] = -t / (float)CN;
            g_count = 0;   // reset for next (deterministic) replay
        }
    }
}

extern "C" void kernel_launch(void* const* d_in, const int* in_sizes, int n_in,
                              void* d_out, int out_size) {
    const float* hazard_pred = (const float*)d_in[0]; // [N,1]
    const float* survtime    = (const float*)d_in[1]; // [N]
    const float* censor      = (const float*)d_in[2]; // [N]
    float* out = (float*)d_out;

    cox_fused_kernel<<<NBLK, NTHR>>>(hazard_pred, survtime, censor, out);
}